// round 4
// baseline (speedup 1.0000x reference)
#include <cuda_runtime.h>

// WindowAttention: B=8192 windows, N=49 tokens, C=128, H=4 heads, HD=32.
// Fully fused fp32: one CTA per window, 256 threads.
//
// SMEM (floats):
//   arr  [128][64] : x^T during qkv GEMM, then attn-out^T for proj GEMM
//   qT   [128][64] : q transposed (row = h*32+d, col = token), pre-scaled
//   kT   [128][64] : k transposed
//   vs   [64][128] : v row-major (token, h*32+d)
//   wsu  [16384]   : union { weight chunk [128][128] } / { ST[4][64][64] }
//   mask_s[2432], ri_s[2432](int), tab_s[704], qb_s[384], pb_s[128]
//
// Padding tokens (49..63) are NEVER zeroed: every consumer of padded data is
// either bounded at 49 (bias add, softmax, AV j-loop) or store-guarded (proj
// output), so garbage/NaN in padded lanes cannot reach out[].

#define NTOK 49
#define CDIM 128
#define NH   4
#define HD   32
#define MP   64

#define OFF_ARR  0
#define OFF_QT   8192
#define OFF_KT   16384
#define OFF_VS   24576
#define OFF_WSU  32768
#define OFF_MASK 49152
#define OFF_RI   51584
#define OFF_TAB  54016
#define OFF_QB   54720
#define OFF_PB   55104
#define SMEM_FLOATS 55232   // 220,928 bytes

__global__ __launch_bounds__(256, 1)
void winattn_fused_kernel(const float* __restrict__ x,
                          const float* __restrict__ mask,
                          const float* __restrict__ qkv_w,
                          const float* __restrict__ qkv_b,
                          const float* __restrict__ btable,
                          const float* __restrict__ proj_w,
                          const float* __restrict__ proj_b,
                          const int*   __restrict__ rel_index,
                          float* __restrict__ out)
{
    extern __shared__ float sm[];
    float* arr    = sm + OFF_ARR;
    float* qT     = sm + OFF_QT;
    float* kT     = sm + OFF_KT;
    float* vs     = sm + OFF_VS;
    float* wsu    = sm + OFF_WSU;
    float* mask_s = sm + OFF_MASK;
    int*   ri_s   = (int*)(sm + OFF_RI);
    float* tab_s  = sm + OFF_TAB;
    float* qb_s   = sm + OFF_QB;
    float* pb_s   = sm + OFF_PB;

    const int tid = threadIdx.x;
    const int b   = blockIdx.x;
    const float scale = 0.17677669529663687f;   // 32^-0.5

    // ---- small tables into smem (overlaps with everything up to attention) --
    if (tid < 384) qb_s[tid] = qkv_b[tid];
    if (tid < 128) pb_s[tid] = proj_b[tid];
    {
        const float* mg = mask + (size_t)b * (NTOK * NTOK);
        for (int t = tid; t < NTOK * NTOK; t += 256) {
            mask_s[t] = mg[t];
            ri_s[t]   = rel_index[t];
        }
        for (int t = tid; t < 169 * NH; t += 256) tab_s[t] = btable[t];
    }

    // ---- load x[b] transposed into arr: arr[c][m] (rows 49..63 left garbage)
    {
        const float* xg = x + (size_t)b * (NTOK * CDIM);
        for (int t = tid; t < NTOK * 32; t += 256) {
            int r  = t >> 5;             // token 0..48
            int c4 = (t & 31) << 2;      // channel (multiple of 4)
            float4 v = *(const float4*)&xg[r * CDIM + c4];
            arr[(c4 + 0) * MP + r] = v.x;
            arr[(c4 + 1) * MP + r] = v.y;
            arr[(c4 + 2) * MP + r] = v.z;
            arr[(c4 + 3) * MP + r] = v.w;
        }
    }

    const int tm = tid & 15, tn = tid >> 4;
    const int m0 = tm * 4,  n0 = tn * 8;

    // ================= qkv GEMM: 3 chunks of 128 cols (q, k, v) =============
    for (int chunk = 0; chunk < 3; chunk++) {
        __syncthreads();   // wsu safe to overwrite; x transpose visible (1st)
        for (int t = tid; t < 128 * 32; t += 256) {
            int r = t >> 5, c4 = (t & 31) << 2;
            *(float4*)&wsu[r * 128 + c4] =
                *(const float4*)&qkv_w[r * 384 + chunk * 128 + c4];
        }
        __syncthreads();

        float acc[4][8];
        #pragma unroll
        for (int i = 0; i < 4; i++)
            #pragma unroll
            for (int j = 0; j < 8; j++) acc[i][j] = 0.f;

        #pragma unroll 8
        for (int k = 0; k < 128; k++) {
            float4 a  = *(const float4*)&arr[k * MP + m0];
            float4 b0 = *(const float4*)&wsu[k * 128 + n0];
            float4 b1 = *(const float4*)&wsu[k * 128 + n0 + 4];
            float av[4] = {a.x, a.y, a.z, a.w};
            float bv[8] = {b0.x, b0.y, b0.z, b0.w, b1.x, b1.y, b1.z, b1.w};
            #pragma unroll
            for (int i = 0; i < 4; i++)
                #pragma unroll
                for (int j = 0; j < 8; j++)
                    acc[i][j] += av[i] * bv[j];
        }

        if (chunk == 0) {               // q: +bias, *scale, store transposed
            #pragma unroll
            for (int j = 0; j < 8; j++) {
                float bb = qb_s[n0 + j];
                #pragma unroll
                for (int i = 0; i < 4; i++)
                    qT[(n0 + j) * MP + m0 + i] = (acc[i][j] + bb) * scale;
            }
        } else if (chunk == 1) {        // k: +bias, store transposed
            #pragma unroll
            for (int j = 0; j < 8; j++) {
                float bb = qb_s[128 + n0 + j];
                #pragma unroll
                for (int i = 0; i < 4; i++)
                    kT[(n0 + j) * MP + m0 + i] = acc[i][j] + bb;
            }
        } else {                        // v: +bias, row-major
            #pragma unroll
            for (int i = 0; i < 4; i++) {
                #pragma unroll
                for (int j = 0; j < 8; j++)
                    vs[(m0 + i) * 128 + n0 + j] = acc[i][j] + qb_s[256 + n0 + j];
            }
        }
    }
    __syncthreads();   // q/k/v visible; wsu free for ST[4][64][64]

    // ================= attention: all 4 heads batched ======================
    // ---- S_h^T[j][i] = sum_d q[i][d]*k[j][d], for all heads, no syncs ----
    {
        const int i0 = (tid & 15) * 4, j0 = (tid >> 4) * 4;
        #pragma unroll
        for (int h = 0; h < NH; h++) {
            float s[4][4];
            #pragma unroll
            for (int i = 0; i < 4; i++)
                #pragma unroll
                for (int j = 0; j < 4; j++) s[i][j] = 0.f;

            const float* qh = qT + h * HD * MP;
            const float* kh = kT + h * HD * MP;
            #pragma unroll 8
            for (int d = 0; d < HD; d++) {
                float4 qa = *(const float4*)&qh[d * MP + i0];
                float4 ka = *(const float4*)&kh[d * MP + j0];
                float qv[4] = {qa.x, qa.y, qa.z, qa.w};
                float kv[4] = {ka.x, ka.y, ka.z, ka.w};
                #pragma unroll
                for (int i = 0; i < 4; i++)
                    #pragma unroll
                    for (int j = 0; j < 4; j++)
                        s[i][j] += qv[i] * kv[j];
            }
            float* STh = wsu + h * 4096;
            #pragma unroll
            for (int j = 0; j < 4; j++)
                #pragma unroll
                for (int i = 0; i < 4; i++)
                    STh[(j0 + j) * MP + i0 + i] = s[i][j];
        }
    }
    __syncthreads();

    // ---- add relative-position bias + mask (all heads) ----
    #pragma unroll
    for (int h = 0; h < NH; h++) {
        float* STh = wsu + h * 4096;
        for (int t = tid; t < NTOK * NTOK; t += 256) {
            int i = t / 49, j = t - i * 49;
            STh[j * MP + i] += tab_s[ri_s[t] * NH + h] + mask_s[t];
        }
    }
    __syncthreads();

    // ---- softmax over keys j: 196 threads = (head, query) pairs ----
    if (tid < NH * NTOK) {
        const int h = tid / NTOK;
        const int i = tid - h * NTOK;
        float* STh = wsu + h * 4096;
        float mx = -1e30f;
        for (int j = 0; j < NTOK; j++) mx = fmaxf(mx, STh[j * MP + i]);
        float ssum = 0.f;
        for (int j = 0; j < NTOK; j++) {
            float e = __expf(STh[j * MP + i] - mx);
            STh[j * MP + i] = e;
            ssum += e;
        }
        float inv = 1.f / ssum;
        for (int j = 0; j < NTOK; j++) STh[j * MP + i] *= inv;
    }
    __syncthreads();

    // ---- O[i][d] = sum_j S[i][j]*v[j][d], all heads, written ^T into arr ---
    {
        const int i0 = (tid & 15) * 4, d0 = (tid >> 4) * 2;
        #pragma unroll
        for (int h = 0; h < NH; h++) {
            float o[4][2];
            #pragma unroll
            for (int i = 0; i < 4; i++) { o[i][0] = 0.f; o[i][1] = 0.f; }

            const float* STh = wsu + h * 4096;
            const float* vb  = vs + h * HD + d0;
            for (int j = 0; j < NTOK; j++) {
                float4 sv = *(const float4*)&STh[j * MP + i0];
                float v0 = vb[j * 128], v1 = vb[j * 128 + 1];
                float svv[4] = {sv.x, sv.y, sv.z, sv.w};
                #pragma unroll
                for (int i = 0; i < 4; i++) {
                    o[i][0] += svv[i] * v0;
                    o[i][1] += svv[i] * v1;
                }
            }
            #pragma unroll
            for (int i = 0; i < 4; i++) {
                arr[(h * HD + d0 + 0) * MP + i0 + i] = o[i][0];
                arr[(h * HD + d0 + 1) * MP + i0 + i] = o[i][1];
            }
        }
    }
    __syncthreads();   // ST reads done; wsu free for proj weights

    // ======================= proj GEMM + output =============================
    for (int t = tid; t < 128 * 32; t += 256) {
        int r = t >> 5, c4 = (t & 31) << 2;
        *(float4*)&wsu[r * 128 + c4] = *(const float4*)&proj_w[r * 128 + c4];
    }
    __syncthreads();

    {
        float acc[4][8];
        #pragma unroll
        for (int i = 0; i < 4; i++)
            #pragma unroll
            for (int j = 0; j < 8; j++) acc[i][j] = 0.f;

        #pragma unroll 8
        for (int k = 0; k < 128; k++) {
            float4 a  = *(const float4*)&arr[k * MP + m0];
            float4 b0 = *(const float4*)&wsu[k * 128 + n0];
            float4 b1 = *(const float4*)&wsu[k * 128 + n0 + 4];
            float av[4] = {a.x, a.y, a.z, a.w};
            float bv[8] = {b0.x, b0.y, b0.z, b0.w, b1.x, b1.y, b1.z, b1.w};
            #pragma unroll
            for (int i = 0; i < 4; i++)
                #pragma unroll
                for (int j = 0; j < 8; j++)
                    acc[i][j] += av[i] * bv[j];
        }

        float* og = out + (size_t)b * (NTOK * CDIM);
        #pragma unroll
        for (int i = 0; i < 4; i++) {
            int m = m0 + i;
            if (m < NTOK) {
                float4 r0, r1;
                r0.x = acc[i][0] + pb_s[n0 + 0];
                r0.y = acc[i][1] + pb_s[n0 + 1];
                r0.z = acc[i][2] + pb_s[n0 + 2];
                r0.w = acc[i][3] + pb_s[n0 + 3];
                r1.x = acc[i][4] + pb_s[n0 + 4];
                r1.y = acc[i][5] + pb_s[n0 + 5];
                r1.z = acc[i][6] + pb_s[n0 + 6];
                r1.w = acc[i][7] + pb_s[n0 + 7];
                *(float4*)&og[m * CDIM + n0]     = r0;
                *(float4*)&og[m * CDIM + n0 + 4] = r1;
            }
        }
    }
}

extern "C" void kernel_launch(void* const* d_in, const int* in_sizes, int n_in,
                              void* d_out, int out_size)
{
    const float* x       = (const float*)d_in[0];
    const float* mask    = (const float*)d_in[1];
    const float* qkv_w   = (const float*)d_in[2];
    const float* qkv_b   = (const float*)d_in[3];
    const float* btable  = (const float*)d_in[4];
    const float* proj_w  = (const float*)d_in[5];
    const float* proj_b  = (const float*)d_in[6];
    const int*   rel_idx = (const int*)d_in[7];
    float*       out     = (float*)d_out;

    const int Bwin = in_sizes[0] / (NTOK * CDIM);   // 8192

    cudaFuncSetAttribute(winattn_fused_kernel,
                         cudaFuncAttributeMaxDynamicSharedMemorySize,
                         SMEM_FLOATS * sizeof(float));

    winattn_fused_kernel<<<Bwin, 256, SMEM_FLOATS * sizeof(float)>>>(
        x, mask, qkv_w, qkv_b, btable, proj_w, proj_b, rel_idx, out);
}

// round 6
// speedup vs baseline: 1.0003x; 1.0003x over previous
#include <cuda_runtime.h>

// WindowAttention: B=8192 windows, N=49 tokens, C=128, H=4 heads, HD=32.
// Fully fused fp32: one CTA per window, 256 threads.
//
// SMEM (floats):
//   arr  [128][64] : x^T during qkv GEMM, then attn-out^T for proj GEMM
//   qT   [128][64] : q transposed (row = h*32+d, col = token), pre-scaled
//   kT   [128][64] : k transposed
//   vs   [64][128] : v row-major (token, h*32+d)
//   wsu  [16384]   : union { weight chunk [128][128] } / { ST[4][64][64] }
//   mask_s[2432], ri_s[2432](int), tab_s[704], qb_s[384], pb_s[128]
//
// Padding tokens (49..63) are NEVER zeroed: every consumer of padded data is
// either bounded at 49 (bias add, softmax, AV j-loop) or store-guarded (proj
// output), so garbage/NaN in padded lanes cannot reach out[].

#define NTOK 49
#define CDIM 128
#define NH   4
#define HD   32
#define MP   64

#define OFF_ARR  0
#define OFF_QT   8192
#define OFF_KT   16384
#define OFF_VS   24576
#define OFF_WSU  32768
#define OFF_MASK 49152
#define OFF_RI   51584
#define OFF_TAB  54016
#define OFF_QB   54720
#define OFF_PB   55104
#define SMEM_FLOATS 55232   // 220,928 bytes

__global__ __launch_bounds__(256, 1)
void winattn_fused_kernel(const float* __restrict__ x,
                          const float* __restrict__ mask,
                          const float* __restrict__ qkv_w,
                          const float* __restrict__ qkv_b,
                          const float* __restrict__ btable,
                          const float* __restrict__ proj_w,
                          const float* __restrict__ proj_b,
                          const int*   __restrict__ rel_index,
                          float* __restrict__ out)
{
    extern __shared__ float sm[];
    float* arr    = sm + OFF_ARR;
    float* qT     = sm + OFF_QT;
    float* kT     = sm + OFF_KT;
    float* vs     = sm + OFF_VS;
    float* wsu    = sm + OFF_WSU;
    float* mask_s = sm + OFF_MASK;
    int*   ri_s   = (int*)(sm + OFF_RI);
    float* tab_s  = sm + OFF_TAB;
    float* qb_s   = sm + OFF_QB;
    float* pb_s   = sm + OFF_PB;

    const int tid = threadIdx.x;
    const int b   = blockIdx.x;
    const float scale = 0.17677669529663687f;   // 32^-0.5

    // ---- small tables into smem (overlaps with everything up to attention) --
    if (tid < 384) qb_s[tid] = qkv_b[tid];
    if (tid < 128) pb_s[tid] = proj_b[tid];
    {
        const float* mg = mask + (size_t)b * (NTOK * NTOK);
        for (int t = tid; t < NTOK * NTOK; t += 256) {
            mask_s[t] = mg[t];
            ri_s[t]   = rel_index[t];
        }
        for (int t = tid; t < 169 * NH; t += 256) tab_s[t] = btable[t];
    }

    // ---- load x[b] transposed into arr: arr[c][m] (rows 49..63 left garbage)
    {
        const float* xg = x + (size_t)b * (NTOK * CDIM);
        for (int t = tid; t < NTOK * 32; t += 256) {
            int r  = t >> 5;             // token 0..48
            int c4 = (t & 31) << 2;      // channel (multiple of 4)
            float4 v = *(const float4*)&xg[r * CDIM + c4];
            arr[(c4 + 0) * MP + r] = v.x;
            arr[(c4 + 1) * MP + r] = v.y;
            arr[(c4 + 2) * MP + r] = v.z;
            arr[(c4 + 3) * MP + r] = v.w;
        }
    }

    const int tm = tid & 15, tn = tid >> 4;
    const int m0 = tm * 4,  n0 = tn * 8;

    // ================= qkv GEMM: 3 chunks of 128 cols (q, k, v) =============
    for (int chunk = 0; chunk < 3; chunk++) {
        __syncthreads();   // wsu safe to overwrite; x transpose visible (1st)
        for (int t = tid; t < 128 * 32; t += 256) {
            int r = t >> 5, c4 = (t & 31) << 2;
            *(float4*)&wsu[r * 128 + c4] =
                *(const float4*)&qkv_w[r * 384 + chunk * 128 + c4];
        }
        __syncthreads();

        float acc[4][8];
        #pragma unroll
        for (int i = 0; i < 4; i++)
            #pragma unroll
            for (int j = 0; j < 8; j++) acc[i][j] = 0.f;

        #pragma unroll 8
        for (int k = 0; k < 128; k++) {
            float4 a  = *(const float4*)&arr[k * MP + m0];
            float4 b0 = *(const float4*)&wsu[k * 128 + n0];
            float4 b1 = *(const float4*)&wsu[k * 128 + n0 + 4];
            float av[4] = {a.x, a.y, a.z, a.w};
            float bv[8] = {b0.x, b0.y, b0.z, b0.w, b1.x, b1.y, b1.z, b1.w};
            #pragma unroll
            for (int i = 0; i < 4; i++)
                #pragma unroll
                for (int j = 0; j < 8; j++)
                    acc[i][j] += av[i] * bv[j];
        }

        if (chunk == 0) {               // q: +bias, *scale, store transposed
            #pragma unroll
            for (int j = 0; j < 8; j++) {
                float bb = qb_s[n0 + j];
                #pragma unroll
                for (int i = 0; i < 4; i++)
                    qT[(n0 + j) * MP + m0 + i] = (acc[i][j] + bb) * scale;
            }
        } else if (chunk == 1) {        // k: +bias, store transposed
            #pragma unroll
            for (int j = 0; j < 8; j++) {
                float bb = qb_s[128 + n0 + j];
                #pragma unroll
                for (int i = 0; i < 4; i++)
                    kT[(n0 + j) * MP + m0 + i] = acc[i][j] + bb;
            }
        } else {                        // v: +bias, row-major
            #pragma unroll
            for (int i = 0; i < 4; i++) {
                #pragma unroll
                for (int j = 0; j < 8; j++)
                    vs[(m0 + i) * 128 + n0 + j] = acc[i][j] + qb_s[256 + n0 + j];
            }
        }
    }
    __syncthreads();   // q/k/v visible; wsu free for ST[4][64][64]

    // ================= attention: all 4 heads batched ======================
    // ---- S_h^T[j][i] = sum_d q[i][d]*k[j][d], for all heads, no syncs ----
    {
        const int i0 = (tid & 15) * 4, j0 = (tid >> 4) * 4;
        #pragma unroll
        for (int h = 0; h < NH; h++) {
            float s[4][4];
            #pragma unroll
            for (int i = 0; i < 4; i++)
                #pragma unroll
                for (int j = 0; j < 4; j++) s[i][j] = 0.f;

            const float* qh = qT + h * HD * MP;
            const float* kh = kT + h * HD * MP;
            #pragma unroll 8
            for (int d = 0; d < HD; d++) {
                float4 qa = *(const float4*)&qh[d * MP + i0];
                float4 ka = *(const float4*)&kh[d * MP + j0];
                float qv[4] = {qa.x, qa.y, qa.z, qa.w};
                float kv[4] = {ka.x, ka.y, ka.z, ka.w};
                #pragma unroll
                for (int i = 0; i < 4; i++)
                    #pragma unroll
                    for (int j = 0; j < 4; j++)
                        s[i][j] += qv[i] * kv[j];
            }
            float* STh = wsu + h * 4096;
            #pragma unroll
            for (int j = 0; j < 4; j++)
                #pragma unroll
                for (int i = 0; i < 4; i++)
                    STh[(j0 + j) * MP + i0 + i] = s[i][j];
        }
    }
    __syncthreads();

    // ---- add relative-position bias + mask (all heads) ----
    #pragma unroll
    for (int h = 0; h < NH; h++) {
        float* STh = wsu + h * 4096;
        for (int t = tid; t < NTOK * NTOK; t += 256) {
            int i = t / 49, j = t - i * 49;
            STh[j * MP + i] += tab_s[ri_s[t] * NH + h] + mask_s[t];
        }
    }
    __syncthreads();

    // ---- softmax over keys j: 196 threads = (head, query) pairs ----
    if (tid < NH * NTOK) {
        const int h = tid / NTOK;
        const int i = tid - h * NTOK;
        float* STh = wsu + h * 4096;
        float mx = -1e30f;
        for (int j = 0; j < NTOK; j++) mx = fmaxf(mx, STh[j * MP + i]);
        float ssum = 0.f;
        for (int j = 0; j < NTOK; j++) {
            float e = __expf(STh[j * MP + i] - mx);
            STh[j * MP + i] = e;
            ssum += e;
        }
        float inv = 1.f / ssum;
        for (int j = 0; j < NTOK; j++) STh[j * MP + i] *= inv;
    }
    __syncthreads();

    // ---- O[i][d] = sum_j S[i][j]*v[j][d], all heads, written ^T into arr ---
    {
        const int i0 = (tid & 15) * 4, d0 = (tid >> 4) * 2;
        #pragma unroll
        for (int h = 0; h < NH; h++) {
            float o[4][2];
            #pragma unroll
            for (int i = 0; i < 4; i++) { o[i][0] = 0.f; o[i][1] = 0.f; }

            const float* STh = wsu + h * 4096;
            const float* vb  = vs + h * HD + d0;
            for (int j = 0; j < NTOK; j++) {
                float4 sv = *(const float4*)&STh[j * MP + i0];
                float v0 = vb[j * 128], v1 = vb[j * 128 + 1];
                float svv[4] = {sv.x, sv.y, sv.z, sv.w};
                #pragma unroll
                for (int i = 0; i < 4; i++) {
                    o[i][0] += svv[i] * v0;
                    o[i][1] += svv[i] * v1;
                }
            }
            #pragma unroll
            for (int i = 0; i < 4; i++) {
                arr[(h * HD + d0 + 0) * MP + i0 + i] = o[i][0];
                arr[(h * HD + d0 + 1) * MP + i0 + i] = o[i][1];
            }
        }
    }
    __syncthreads();   // ST reads done; wsu free for proj weights

    // ======================= proj GEMM + output =============================
    for (int t = tid; t < 128 * 32; t += 256) {
        int r = t >> 5, c4 = (t & 31) << 2;
        *(float4*)&wsu[r * 128 + c4] = *(const float4*)&proj_w[r * 128 + c4];
    }
    __syncthreads();

    {
        float acc[4][8];
        #pragma unroll
        for (int i = 0; i < 4; i++)
            #pragma unroll
            for (int j = 0; j < 8; j++) acc[i][j] = 0.f;

        #pragma unroll 8
        for (int k = 0; k < 128; k++) {
            float4 a  = *(const float4*)&arr[k * MP + m0];
            float4 b0 = *(const float4*)&wsu[k * 128 + n0];
            float4 b1 = *(const float4*)&wsu[k * 128 + n0 + 4];
            float av[4] = {a.x, a.y, a.z, a.w};
            float bv[8] = {b0.x, b0.y, b0.z, b0.w, b1.x, b1.y, b1.z, b1.w};
            #pragma unroll
            for (int i = 0; i < 4; i++)
                #pragma unroll
                for (int j = 0; j < 8; j++)
                    acc[i][j] += av[i] * bv[j];
        }

        float* og = out + (size_t)b * (NTOK * CDIM);
        #pragma unroll
        for (int i = 0; i < 4; i++) {
            int m = m0 + i;
            if (m < NTOK) {
                float4 r0, r1;
                r0.x = acc[i][0] + pb_s[n0 + 0];
                r0.y = acc[i][1] + pb_s[n0 + 1];
                r0.z = acc[i][2] + pb_s[n0 + 2];
                r0.w = acc[i][3] + pb_s[n0 + 3];
                r1.x = acc[i][4] + pb_s[n0 + 4];
                r1.y = acc[i][5] + pb_s[n0 + 5];
                r1.z = acc[i][6] + pb_s[n0 + 6];
                r1.w = acc[i][7] + pb_s[n0 + 7];
                *(float4*)&og[m * CDIM + n0]     = r0;
                *(float4*)&og[m * CDIM + n0 + 4] = r1;
            }
        }
    }
}

extern "C" void kernel_launch(void* const* d_in, const int* in_sizes, int n_in,
                              void* d_out, int out_size)
{
    const float* x       = (const float*)d_in[0];
    const float* mask    = (const float*)d_in[1];
    const float* qkv_w   = (const float*)d_in[2];
    const float* qkv_b   = (const float*)d_in[3];
    const float* btable  = (const float*)d_in[4];
    const float* proj_w  = (const float*)d_in[5];
    const float* proj_b  = (const float*)d_in[6];
    const int*   rel_idx = (const int*)d_in[7];
    float*       out     = (float*)d_out;

    const int Bwin = in_sizes[0] / (NTOK * CDIM);   // 8192

    cudaFuncSetAttribute(winattn_fused_kernel,
                         cudaFuncAttributeMaxDynamicSharedMemorySize,
                         SMEM_FLOATS * sizeof(float));

    winattn_fused_kernel<<<Bwin, 256, SMEM_FLOATS * sizeof(float)>>>(
        x, mask, qkv_w, qkv_b, btable, proj_w, proj_b, rel_idx, out);
}